// round 10
// baseline (speedup 1.0000x reference)
#include <cuda_runtime.h>

#define FULLMASK 0xffffffffu

constexpr int   B_     = 256;
constexpr int   T_     = 256;
constexpr int   C_     = 1024;
constexpr int   L_     = 32;
constexpr int   S_     = 65;      // 2*L+1 extended states
constexpr int   SP_    = 34;      // compact row: [blank, lab0..lab31, pad]
constexpr int   BLANK_ = C_ - 1;
constexpr float PRE    = 512.0f;  // 2^9 per-step prescale
constexpr int   PRE_E  = 9;
constexpr float EPS    = 1e-7f;
constexpr float EPS_S  = EPS * PRE;

constexpr int   NSCAN  = B_;          // 256 scan CTAs (bids 0..255, first)

// compact gathered probs (8.9 MB) + per-(batch,chunk) ready flags
__device__ float g_scr[(size_t)B_ * T_ * SP_];
__device__ int   g_cflag[B_][8];      // zero-init; self-resetting per run

__device__ __forceinline__ int kidx(int s) {
    return (s >= S_) ? 33 : ((s & 1) ? ((s >> 1) + 1) : 0);
}
__device__ __forceinline__ float allow_fwd(int s, const int* labs) {
    if (!(s & 1) || s >= S_) return 0.0f;
    const int j = (s - 1) >> 1;
    return (j == 0 || labs[j] != labs[j - 1]) ? 1.0f : 0.0f;
}
__device__ __forceinline__ float allow_bwd(int s, const int* labs) {
    if (!(s & 1) || (s + 2) > S_ - 1) return 0.0f;
    const int jn = (s + 1) >> 1, jp = (s - 1) >> 1;
    return (labs[jn] != labs[jp]) ? 1.0f : 0.0f;
}
__device__ __forceinline__ int renorm(float& r0, float& r1, float& r2) {
    float m = fmaxf(fmaxf(r0, r1), r2);
    int im = __float_as_int(m);
    asm volatile("redux.sync.max.s32 %0, %1, 0xffffffff;" : "=r"(im) : "r"(im));
    const int e = (im >> 23) - 127;
    const float sc = __int_as_float((127 - e) << 23);  // exact 2^-e
    r0 *= sc; r1 *= sc; r2 *= sc;
    return e;
}
__device__ __forceinline__ float ldg_cg(const float* p) {
    float v;
    asm volatile("ld.global.cg.f32 %0, [%1];" : "=f"(v) : "l"(p));
    return v;
}
__device__ __forceinline__ int ld_acq(const int* p) {
    int v;
    asm volatile("ld.global.acquire.gpu.b32 %0, [%1];" : "=r"(v) : "l"(p) : "memory");
    return v;
}

__global__ __launch_bounds__(256, 6)
void ctc_pipe_kernel(const int* __restrict__ y_true,
                     const float* __restrict__ y_pred,
                     float* __restrict__ out)
{
    // union-style shared: gather CTAs use labsx only; scan CTAs use the rest
    __shared__ __align__(16) float bufF[32 * SP_];   // 4352 B (warp 0)
    __shared__ __align__(16) float bufB[32 * SP_];   // 4352 B (warp 1)
    __shared__ int   labs[L_];
    __shared__ int   labsx[33];
    __shared__ float exB[66];
    __shared__ int   exE1;

    const int bid  = blockIdx.x;
    const int tid  = threadIdx.x;
    const int lane = tid & 31;
    const int wid  = tid >> 5;

    // ===================== GATHER CTAs (bids 256 .. 2303) ===================
    if (bid >= NSCAN) {
        const int g     = bid - NSCAN;          // 0..2047
        const int phase = g >> 9;               // 0..3
        const int r     = g & 511;
        const int b     = r >> 1;
        const int side  = r & 1;
        const int chunk = (side ? (7 - phase) : phase) << 5;

        if (tid < 33)
            labsx[tid] = tid ? __ldg(y_true + b * L_ + tid - 1) : BLANK_;
        __syncthreads();

        const float* base = y_pred + ((size_t)b * T_ + chunk) * C_;

        float v[5];
        int   rr[5], cc[5];
#pragma unroll
        for (int i = 0; i < 5; ++i) {
            const int f = tid + i * 256;
            if (f < 1056) {
                const int row = f / 33;
                const int c   = f - 33 * row;
                rr[i] = row; cc[i] = c;
                v[i]  = ldg_cg(base + (size_t)row * C_ + labsx[c]);
            }
        }
        float* orow = g_scr + ((size_t)b * T_ + chunk) * SP_;
#pragma unroll
        for (int i = 0; i < 5; ++i) {
            const int f = tid + i * 256;
            if (f < 1056)
                orow[rr[i] * SP_ + cc[i]] = fmaf(v[i], PRE, EPS_S);
        }
        __threadfence();
        __syncthreads();
        if (tid == 0) atomicExch(&g_cflag[b][chunk >> 5], 1);
        return;
    }

    // ===================== SCAN CTAs (bids 0 .. 255) ========================
    const int b = bid;
    if (wid >= 2) return;            // free 6 warps immediately

    if (tid < L_) labs[tid] = __ldg(y_true + b * L_ + tid);
    asm volatile("bar.sync 1, 64;" ::: "memory");

    const int s0 = 3 * lane, s1 = s0 + 1, s2 = s0 + 2;
    const int k0 = kidx(s0), k1 = kidx(s1), k2 = kidx(s2);

    if (wid == 0) {
        // -------- forward: alpha_0 .. alpha_127, chunks 0,1,2,3 --------
        const float a0 = allow_fwd(s0, labs);
        const float a1 = allow_fwd(s1, labs);
        const float a2 = allow_fwd(s2, labs);
        float r0 = 0.0f, r1 = 0.0f, r2 = 0.0f;
        int   E  = 0;

#define FSTEP(rr) {                                                  \
            const float* sr = bufF + (rr) * SP_;                     \
            const float p0 = sr[k0], p1 = sr[k1], p2 = sr[k2];       \
            float u1 = __shfl_up_sync(FULLMASK, r1, 1);              \
            float u2 = __shfl_up_sync(FULLMASK, r2, 1);              \
            u1 = lane ? u1 : 0.0f;                                   \
            u2 = lane ? u2 : 0.0f;                                   \
            const float n0 = p0 * fmaf(a0, u1, r0 + u2);             \
            const float n1 = p1 * fmaf(a1, u2, r1 + r0);             \
            const float n2 = p2 * fmaf(a2, r0, r2 + r1);             \
            r0 = n0; r1 = n1; r2 = n2; }

        for (int i = 0; i < 4; ++i) {
            if (lane == 0) { while (!ld_acq(&g_cflag[b][i])) __nanosleep(64); }
            __syncwarp();
            // copy chunk i (rows 32i..32i+31) into bufF
            {
                const float4* src =
                    (const float4*)(g_scr + ((size_t)b * T_ + 32 * i) * SP_);
                float4* dst = (float4*)bufF;
                for (int x = lane; x < (32 * SP_) / 4; x += 32)
                    dst[x] = src[x];
            }
            __syncwarp();
            if (i == 0) {
                if (lane == 0) { r0 = bufF[0]; r1 = bufF[1]; }
#pragma unroll
                for (int j = 1; j < 8; ++j) FSTEP(j);
                E += renorm(r0, r1, r2);
#pragma unroll
                for (int g2 = 1; g2 < 4; ++g2) {
#pragma unroll
                    for (int j = 0; j < 8; ++j) FSTEP(g2 * 8 + j);
                    E += renorm(r0, r1, r2);
                }
            } else {
#pragma unroll
                for (int g2 = 0; g2 < 4; ++g2) {
#pragma unroll
                    for (int j = 0; j < 8; ++j) FSTEP(g2 * 8 + j);
                    E += renorm(r0, r1, r2);
                }
            }
        }
#undef FSTEP

        // wait for warp 1's beta, then combine
        asm volatile("bar.sync 1, 64;" ::: "memory");
        float part = 0.0f;
        if (lane < 22)
            part = r0 * exB[s0] + r1 * exB[s1] + r2 * exB[s2];
#pragma unroll
        for (int o = 16; o; o >>= 1)
            part += __shfl_xor_sync(FULLMASK, part, o);
        if (lane == 0) {
            const float LN2 = 0.6931471805599453f;
            out[b] = -(logf(part) +
                       (float)(E + exE1 - PRE_E * T_) * LN2);
        }
        // reset flags for graph replay (all 8 consumed by now)
        if (lane < 8) g_cflag[b][lane] = 0;
    }
    else {
        // -------- backward: c_t = p_t*beta_t, t=255..128, chunks 7,6,5,4 ----
        const int lab = labs[lane];
        const unsigned nzm = __ballot_sync(FULLMASK, lab != 0);
        const int len = __popc(nzm);
        int ilb = 2 * len;
        int ill = 2 * len - 1;
        if (ill < 0) ill += S_;

        const float a0 = allow_bwd(s0, labs);
        const float a1 = allow_bwd(s1, labs);
        const float a2 = allow_bwd(s2, labs);
        float r0 = 0.0f, r1 = 0.0f, r2 = 0.0f;
        int   E  = 0;

#define BSTEP(rr) {                                                  \
            const float* sr = bufB + (rr) * SP_;                     \
            const float p0 = sr[k0], p1 = sr[k1], p2 = sr[k2];       \
            const float u0 = __shfl_down_sync(FULLMASK, r0, 1);      \
            const float u1 = __shfl_down_sync(FULLMASK, r1, 1);      \
            const float n0 = p0 * fmaf(a0, r2, r0 + r1);             \
            const float n1 = p1 * fmaf(a1, u0, r1 + r2);             \
            const float n2 = p2 * fmaf(a2, u1, r2 + u0);             \
            r0 = n0; r1 = n1; r2 = n2; }

        for (int i = 0; i < 4; ++i) {
            const int ch = 7 - i;
            if (lane == 0) { while (!ld_acq(&g_cflag[b][ch])) __nanosleep(64); }
            __syncwarp();
            // copy chunk ch (rows 32ch..32ch+31 == t 224-32i .. 255-32i)
            {
                const float4* src =
                    (const float4*)(g_scr + ((size_t)b * T_ + 32 * ch) * SP_);
                float4* dst = (float4*)bufB;
                for (int x = lane; x < (32 * SP_) / 4; x += 32)
                    dst[x] = src[x];
            }
            __syncwarp();
            if (i == 0) {
                const float* sr = bufB + 31 * SP_;   // t = 255
                r0 = (s0 == ilb || s0 == ill) ? sr[k0] : 0.0f;
                r1 = (s1 == ilb || s1 == ill) ? sr[k1] : 0.0f;
                r2 = (s2 == ilb || s2 == ill) ? sr[k2] : 0.0f;
#pragma unroll
                for (int j = 30; j > 23; --j) BSTEP(j);
                E += renorm(r0, r1, r2);
#pragma unroll
                for (int g2 = 1; g2 < 4; ++g2) {
#pragma unroll
                    for (int j = 0; j < 8; ++j) BSTEP(23 - (g2 - 1) * 8 - j);
                    E += renorm(r0, r1, r2);
                }
            } else {
#pragma unroll
                for (int g2 = 0; g2 < 4; ++g2) {
#pragma unroll
                    for (int j = 0; j < 8; ++j) BSTEP(31 - g2 * 8 - j);
                    E += renorm(r0, r1, r2);
                }
            }
        }
#undef BSTEP

        // beta_127 combine (no p multiply) from c_128
        const float u0 = __shfl_down_sync(FULLMASK, r0, 1);
        const float u1 = __shfl_down_sync(FULLMASK, r1, 1);
        const float B0 = fmaf(a0, r2, r0 + r1);
        const float B1 = fmaf(a1, u0, r1 + r2);
        const float B2 = fmaf(a2, u1, r2 + u0);
        if (lane < 22) { exB[s0] = B0; exB[s1] = B1; exB[s2] = B2; }
        if (lane == 0) exE1 = E;
        asm volatile("bar.sync 1, 64;" ::: "memory");
    }
}

extern "C" void kernel_launch(void* const* d_in, const int* in_sizes, int n_in,
                              void* d_out, int out_size)
{
    (void)n_in; (void)out_size;
    const int*   y_true;
    const float* y_pred;
    if (in_sizes[0] == B_ * L_) {
        y_true = (const int*)d_in[0];
        y_pred = (const float*)d_in[1];
    } else {
        y_true = (const int*)d_in[1];
        y_pred = (const float*)d_in[0];
    }
    ctc_pipe_kernel<<<NSCAN + B_ * 8, 256>>>(y_true, y_pred, (float*)d_out);
}

// round 11
// speedup vs baseline: 1.9877x; 1.9877x over previous
#include <cuda_runtime.h>

#define FULLMASK 0xffffffffu

constexpr int   B_     = 256;
constexpr int   T_     = 256;
constexpr int   C_     = 1024;
constexpr int   L_     = 32;
constexpr int   S_     = 65;      // 2*L+1 extended states
constexpr int   SP_    = 34;      // compact row: [blank, lab0..lab31, pad]
constexpr int   BLANK_ = C_ - 1;
constexpr float PRE    = 512.0f;  // 2^9 per-step prescale
constexpr int   PRE_E  = 9;
constexpr float EPS    = 1e-7f;
constexpr float EPS_S  = EPS * PRE;

// compact gathered probs (8.9 MB) + coordination state (all zero-init,
// self-resetting each run for graph replay)
__device__ float g_scr[(size_t)B_ * T_ * SP_];
__device__ int   g_cnt[2][B_];        // per-(half,batch) completed-chunk count
__device__ int   g_done[B_];          // per-batch published-half count
__device__ float g_ex[2][B_][66];     // boundary states (alpha_127 / beta_127)
__device__ int   g_exE[2][B_];        // accumulated renorm exponents

__device__ __forceinline__ int kidx(int s) {
    return (s >= S_) ? 33 : ((s & 1) ? ((s >> 1) + 1) : 0);
}
__device__ __forceinline__ float allow_fwd(int s, const int* labs) {
    if (!(s & 1) || s >= S_) return 0.0f;
    const int j = (s - 1) >> 1;
    return (j == 0 || labs[j] != labs[j - 1]) ? 1.0f : 0.0f;
}
__device__ __forceinline__ float allow_bwd(int s, const int* labs) {
    if (!(s & 1) || (s + 2) > S_ - 1) return 0.0f;
    const int jn = (s + 1) >> 1, jp = (s - 1) >> 1;
    return (labs[jn] != labs[jp]) ? 1.0f : 0.0f;
}
__device__ __forceinline__ int renorm(float& r0, float& r1, float& r2) {
    float m = fmaxf(fmaxf(r0, r1), r2);
    int im = __float_as_int(m);
    asm volatile("redux.sync.max.s32 %0, %1, 0xffffffff;" : "=r"(im) : "r"(im));
    const int e = (im >> 23) - 127;
    const float sc = __int_as_float((127 - e) << 23);  // exact 2^-e
    r0 *= sc; r1 *= sc; r2 *= sc;
    return e;
}
__device__ __forceinline__ float ldg_cg(const float* p) {
    float v;
    asm volatile("ld.global.cg.f32 %0, [%1];" : "=f"(v) : "l"(p));
    return v;
}

__global__ __launch_bounds__(256)
void ctc_fused_kernel(const int* __restrict__ y_true,
                      const float* __restrict__ y_pred,
                      float* __restrict__ out)
{
    __shared__ int   labsx[33];                    // [blank, lab0..lab31]
    __shared__ __align__(16) float slab[128 * SP_]; // 17408 B (scan path only)
    __shared__ int   s_role;

    const int bid   = blockIdx.x;
    const int b     = bid >> 3;
    const int cidx  = bid & 7;                 // chunk index 0..7
    const int chunk = cidx << 5;               // row base
    const int half  = cidx >> 2;               // 0: rows 0..127, 1: 128..255
    const int tid   = threadIdx.x;
    const int lane  = tid & 31;
    const int wid   = tid >> 5;

    if (tid < 33)
        labsx[tid] = tid ? __ldg(y_true + b * L_ + tid - 1) : BLANK_;
    __syncthreads();

    // ---------------- gather this CTA's 32-row chunk (proven R6 code) -------
    {
        const float* base = y_pred + ((size_t)b * T_ + chunk) * C_;
        float v[5];
        int   rr[5], cc[5];
#pragma unroll
        for (int i = 0; i < 5; ++i) {
            const int f = tid + i * 256;
            if (f < 1056) {
                const int row = f / 33;
                const int c   = f - 33 * row;
                rr[i] = row; cc[i] = c;
                v[i]  = ldg_cg(base + (size_t)row * C_ + labsx[c]);
            }
        }
        float* orow = g_scr + ((size_t)b * T_ + chunk) * SP_;
#pragma unroll
        for (int i = 0; i < 5; ++i) {
            const int f = tid + i * 256;
            if (f < 1056)
                orow[rr[i] * SP_ + cc[i]] = fmaf(v[i], PRE, EPS_S);
        }
    }
    __threadfence();
    __syncthreads();

    // ---------------- last arriver of this half becomes the scanner ---------
    if (tid == 0)
        s_role = (atomicAdd(&g_cnt[half][b], 1) == 3);
    __syncthreads();
    if (!s_role) return;

    // copy this half's 128 rows (L2-hot) into smem; pad col 33
    {
        const float4* src =
            (const float4*)(g_scr + ((size_t)b * T_ + 128 * half) * SP_);
        float4* dst = (float4*)slab;
        for (int i = tid; i < (128 * SP_) / 4; i += 256)
            dst[i] = src[i];
    }
    if (tid < 128) slab[tid * SP_ + 33] = 0.0f;
    __syncthreads();

    if (wid != 0) return;    // only warp 0 scans; CTA stays until it's done

    const int* labs = labsx + 1;
    const int s0 = 3 * lane, s1 = s0 + 1, s2 = s0 + 2;
    const int k0 = kidx(s0), k1 = kidx(s1), k2 = kidx(s2);

    float r0 = 0.0f, r1 = 0.0f, r2 = 0.0f;
    int   E  = 0;

    if (half == 0) {
        // ---------------- forward: alpha_0 .. alpha_127 (local rows) --------
        const float a0 = allow_fwd(s0, labs);
        const float a1 = allow_fwd(s1, labs);
        const float a2 = allow_fwd(s2, labs);
        if (lane == 0) { r0 = slab[0]; r1 = slab[1]; }

#define FSTEP(tt) {                                                  \
            const float* sr = slab + (tt) * SP_;                     \
            const float p0 = sr[k0], p1 = sr[k1], p2 = sr[k2];       \
            float u1 = __shfl_up_sync(FULLMASK, r1, 1);              \
            float u2 = __shfl_up_sync(FULLMASK, r2, 1);              \
            u1 = lane ? u1 : 0.0f;                                   \
            u2 = lane ? u2 : 0.0f;                                   \
            const float n0 = p0 * fmaf(a0, u1, r0 + u2);             \
            const float n1 = p1 * fmaf(a1, u2, r1 + r0);             \
            const float n2 = p2 * fmaf(a2, r0, r2 + r1);             \
            r0 = n0; r1 = n1; r2 = n2; }

#pragma unroll
        for (int j = 1; j < 8; ++j) FSTEP(j);
        E += renorm(r0, r1, r2);
        for (int tb = 8; tb < 128; tb += 8) {
#pragma unroll
            for (int j = 0; j < 8; ++j) FSTEP(tb + j);
            E += renorm(r0, r1, r2);
        }
#undef FSTEP
    } else {
        // -------- backward: c_t = p_t * beta_t, global t=255..128 -----------
        const int lab = labs[lane];
        const unsigned nzm = __ballot_sync(FULLMASK, lab != 0);
        const int len = __popc(nzm);
        int ilb = 2 * len;
        int ill = 2 * len - 1;
        if (ill < 0) ill += S_;

        const float a0 = allow_bwd(s0, labs);
        const float a1 = allow_bwd(s1, labs);
        const float a2 = allow_bwd(s2, labs);
        {
            const float* sr = slab + 127 * SP_;   // global t = 255
            r0 = (s0 == ilb || s0 == ill) ? sr[k0] : 0.0f;
            r1 = (s1 == ilb || s1 == ill) ? sr[k1] : 0.0f;
            r2 = (s2 == ilb || s2 == ill) ? sr[k2] : 0.0f;
        }

#define BSTEP(tt) {                                                  \
            const float* sr = slab + (tt) * SP_;                     \
            const float p0 = sr[k0], p1 = sr[k1], p2 = sr[k2];       \
            const float u0 = __shfl_down_sync(FULLMASK, r0, 1);      \
            const float u1 = __shfl_down_sync(FULLMASK, r1, 1);      \
            const float n0 = p0 * fmaf(a0, r2, r0 + r1);             \
            const float n1 = p1 * fmaf(a1, u0, r1 + r2);             \
            const float n2 = p2 * fmaf(a2, u1, r2 + u0);             \
            r0 = n0; r1 = n1; r2 = n2; }

#pragma unroll
        for (int j = 126; j > 119; --j) BSTEP(j);   // t = 254..248
        E += renorm(r0, r1, r2);
        for (int tb = 119; tb >= 7; tb -= 8) {       // t = 247..128
#pragma unroll
            for (int j = 0; j < 8; ++j) BSTEP(tb - j);
            E += renorm(r0, r1, r2);
        }
#undef BSTEP

        // beta_127 combine (no p multiply) from c_128
        const float u0 = __shfl_down_sync(FULLMASK, r0, 1);
        const float u1 = __shfl_down_sync(FULLMASK, r1, 1);
        const float B0 = fmaf(a0, r2, r0 + r1);
        const float B1 = fmaf(a1, u0, r1 + r2);
        const float B2 = fmaf(a2, u1, r2 + u0);
        r0 = B0; r1 = B1; r2 = B2;
    }

    // ---------------- publish and combine across halves ---------------------
    if (lane < 22) {
        g_ex[half][b][s0] = r0;
        g_ex[half][b][s1] = r1;
        g_ex[half][b][s2] = r2;
    }
    int oldd = 0;
    if (lane == 0) {
        g_exE[half][b] = E;
        __threadfence();
        oldd = atomicAdd(&g_done[b], 1);
        g_cnt[half][b] = 0;            // reset for next replay
    }
    oldd = __shfl_sync(FULLMASK, oldd, 0);

    if (oldd == 1) {
        __threadfence();               // acquire the other half's publishes
        float part = 0.0f;
        if (lane < 22) {
            part  = ldg_cg(&g_ex[0][b][s0]) * ldg_cg(&g_ex[1][b][s0]);
            part += ldg_cg(&g_ex[0][b][s1]) * ldg_cg(&g_ex[1][b][s1]);
            part += ldg_cg(&g_ex[0][b][s2]) * ldg_cg(&g_ex[1][b][s2]);
        }
#pragma unroll
        for (int o = 16; o; o >>= 1)
            part += __shfl_xor_sync(FULLMASK, part, o);
        if (lane == 0) {
            int e0, e1;
            asm volatile("ld.global.cg.s32 %0, [%1];" : "=r"(e0) : "l"(&g_exE[0][b]));
            asm volatile("ld.global.cg.s32 %0, [%1];" : "=r"(e1) : "l"(&g_exE[1][b]));
            const float LN2 = 0.6931471805599453f;
            out[b] = -(logf(part) + (float)(e0 + e1 - PRE_E * T_) * LN2);
            g_done[b] = 0;             // reset for next replay
        }
    }
}

extern "C" void kernel_launch(void* const* d_in, const int* in_sizes, int n_in,
                              void* d_out, int out_size)
{
    (void)n_in; (void)out_size;
    const int*   y_true;
    const float* y_pred;
    if (in_sizes[0] == B_ * L_) {
        y_true = (const int*)d_in[0];
        y_pred = (const float*)d_in[1];
    } else {
        y_true = (const int*)d_in[1];
        y_pred = (const float*)d_in[0];
    }
    ctc_fused_kernel<<<B_ * 8, 256>>>(y_true, y_pred, (float*)d_out);
}